// round 1
// baseline (speedup 1.0000x reference)
#include <cuda_runtime.h>
#include <math.h>

#define BB 4
#define LSEQ 2048
#define DMODEL 1024
#define DINNER 2048
#define DSTATE 16
#define DTRANK 128
#define XPDIM 160           // DTRANK + 2*DSTATE
#define MTOT (BB*LSEQ)      // 8192

// ---------------- scratch (allocation-free rule: __device__ globals) ----------
static __device__ float g_xr  [(size_t)MTOT * 2 * DINNER]; // in_proj out: [m, 4096] (xc | res)
static __device__ float g_xc  [(size_t)MTOT * DINNER];     // conv out
static __device__ float g_xdbl[(size_t)MTOT * XPDIM];      // x_proj out
static __device__ float g_dlt [(size_t)MTOT * DINNER];     // softplus(dt_proj)
static __device__ float g_z   [(size_t)MTOT * DINNER];     // y * silu(res)

// ---------------- generic NT GEMM: C[m,n] = sum_k A[m,k]*B[n,k] (+bias,+epi) --
// EPI: 0 = bias add, 1 = bias add + softplus
template<int BM,int BN,int BK,int TM,int TN,int EPI>
__global__ void __launch_bounds__((BM/TM)*(BN/TN))
gemm_nt(const float* __restrict__ A, int lda,
        const float* __restrict__ Bm, int ldb,
        float* __restrict__ C, int ldc,
        const float* __restrict__ bias, int K)
{
    constexpr int TX = BN / TN;
    constexpr int TY = BM / TM;
    constexpr int NT = TX * TY;
    constexpr int KQ = BK / 4;
    constexpr int AF4 = BM * BK / 4 / NT;
    constexpr int BF4 = BN * BK / 4 / NT;

    __shared__ float As[BK][BM + 1];
    __shared__ float Bs[BK][BN + 1];

    const int tid = threadIdx.x;
    const int tx = tid % TX, ty = tid / TX;
    const int m0 = blockIdx.y * BM, n0 = blockIdx.x * BN;

    float acc[TM][TN];
#pragma unroll
    for (int i = 0; i < TM; i++)
#pragma unroll
        for (int j = 0; j < TN; j++) acc[i][j] = 0.f;

    for (int k0 = 0; k0 < K; k0 += BK) {
#pragma unroll
        for (int i = 0; i < AF4; i++) {
            int idx = tid + i * NT;
            int r = idx / KQ, kq = idx % KQ;
            float4 v = *(const float4*)(A + (size_t)(m0 + r) * lda + k0 + kq * 4);
            As[kq*4+0][r] = v.x; As[kq*4+1][r] = v.y;
            As[kq*4+2][r] = v.z; As[kq*4+3][r] = v.w;
        }
#pragma unroll
        for (int i = 0; i < BF4; i++) {
            int idx = tid + i * NT;
            int r = idx / KQ, kq = idx % KQ;
            float4 v = *(const float4*)(Bm + (size_t)(n0 + r) * ldb + k0 + kq * 4);
            Bs[kq*4+0][r] = v.x; Bs[kq*4+1][r] = v.y;
            Bs[kq*4+2][r] = v.z; Bs[kq*4+3][r] = v.w;
        }
        __syncthreads();
#pragma unroll
        for (int k = 0; k < BK; k++) {
            float ra[TM], rb[TN];
#pragma unroll
            for (int i = 0; i < TM; i++) ra[i] = As[k][ty * TM + i];
#pragma unroll
            for (int j = 0; j < TN; j++) {
                int c = (TN == 8) ? ((j < 4) ? tx * 4 + j : BN / 2 + tx * 4 + (j - 4))
                                  : tx * TN + j;
                rb[j] = Bs[k][c];
            }
#pragma unroll
            for (int i = 0; i < TM; i++)
#pragma unroll
                for (int j = 0; j < TN; j++)
                    acc[i][j] += ra[i] * rb[j];
        }
        __syncthreads();
    }

    // epilogue
#pragma unroll
    for (int i = 0; i < TM; i++) {
        int m = m0 + ty * TM + i;
        if (TN == 8) {
#pragma unroll
            for (int g = 0; g < 2; g++) {
                int n = n0 + g * (BN / 2) + tx * 4;
                float4 v;
                float* pv = &v.x;
#pragma unroll
                for (int q = 0; q < 4; q++) {
                    float t = acc[i][g * 4 + q];
                    if (bias) t += bias[n + q];
                    if (EPI == 1) t = fmaxf(t, 0.f) + log1pf(expf(-fabsf(t)));
                    pv[q] = t;
                }
                *(float4*)(C + (size_t)m * ldc + n) = v;
            }
        } else {
#pragma unroll
            for (int j = 0; j < TN; j++) {
                int n = n0 + tx * TN + j;
                float t = acc[i][j];
                if (bias) t += bias[n];
                if (EPI == 1) t = fmaxf(t, 0.f) + log1pf(expf(-fabsf(t)));
                C[(size_t)m * ldc + n] = t;
            }
        }
    }
}

// ---------------- depthwise conv1d, k=4, pad (1,2): out[t]=sum_j w[j]*x[t-1+j] --
__global__ void conv_k(const float* __restrict__ xr,   // [m, 4096], xc = cols [0,2048)
                       const float* __restrict__ w,    // [2048, 1, 4]
                       const float* __restrict__ cb,   // [2048]
                       float* __restrict__ out)        // [m, 2048]
{
    int idx = blockIdx.x * blockDim.x + threadIdx.x;
    if (idx >= MTOT * DINNER) return;
    int d = idx % DINNER;
    int m = idx / DINNER;
    int t = m % LSEQ;
    int b = m / LSEQ;
    float acc = cb[d];
#pragma unroll
    for (int j = 0; j < 4; j++) {
        int tt = t - 1 + j;
        if (tt >= 0 && tt < LSEQ)
            acc += w[d * 4 + j] * xr[(size_t)(b * LSEQ + tt) * (2 * DINNER) + d];
    }
    out[idx] = acc;
}

// ---------------- selective scan + D skip + silu gating --------------------
// one thread per (b,d) channel, 16 states in registers; B/C staged in smem
#define SCAN_T 128
#define SCAN_D 64
__global__ void __launch_bounds__(SCAN_D)
scan_k(const float* __restrict__ xdbl,   // [m, 160]  (B at 128..143, C at 144..159)
       const float* __restrict__ delta,  // [m, 2048]
       const float* __restrict__ u,      // [m, 2048] (conv out)
       const float* __restrict__ xr,     // [m, 4096] (res = cols 2048..)
       const float* __restrict__ Alog,   // [2048, 16]
       const float* __restrict__ Dp,     // [2048]
       float* __restrict__ z)            // [m, 2048]
{
    __shared__ float4 sBC[SCAN_T][8];    // per t: B = f4[0..3], C = f4[4..7]

    const int b = blockIdx.x / (DINNER / SCAN_D);
    const int d = (blockIdx.x % (DINNER / SCAN_D)) * SCAN_D + threadIdx.x;

    float a[DSTATE];
#pragma unroll
    for (int n = 0; n < DSTATE; n++) a[n] = -__expf(Alog[d * DSTATE + n]);

    // detect geometric structure A_n ~= (n+1)*A_0 (true for this model family);
    // enables 1-exp pow-chain instead of 16 MUFU per step. Falls back otherwise.
    bool geo = true;
#pragma unroll
    for (int n = 1; n < DSTATE; n++)
        geo = geo && (fabsf(a[n] - (float)(n + 1) * a[0]) <= 1e-4f * (float)(n + 1) * fabsf(a[0]));

    const float dd = Dp[d];
    float h[DSTATE];
#pragma unroll
    for (int n = 0; n < DSTATE; n++) h[n] = 0.f;

    for (int t0 = 0; t0 < LSEQ; t0 += SCAN_T) {
        __syncthreads();
        for (int i = threadIdx.x; i < SCAN_T * 8; i += SCAN_D) {
            int tt = i >> 3, q = i & 7;
            sBC[tt][q] = *(const float4*)(xdbl + (size_t)(b * LSEQ + t0 + tt) * XPDIM + DTRANK + q * 4);
        }
        __syncthreads();

        for (int tt = 0; tt < SCAN_T; tt++) {
            size_t m = (size_t)(b * LSEQ + t0 + tt);
            float dlt = delta[m * DINNER + d];
            float uu  = u[m * DINNER + d];
            float du = dlt * uu;

            float bv[DSTATE], cv[DSTATE];
#pragma unroll
            for (int q = 0; q < 4; q++) {
                float4 vb = sBC[tt][q];
                bv[q*4+0]=vb.x; bv[q*4+1]=vb.y; bv[q*4+2]=vb.z; bv[q*4+3]=vb.w;
                float4 vc = sBC[tt][4+q];
                cv[q*4+0]=vc.x; cv[q*4+1]=vc.y; cv[q*4+2]=vc.z; cv[q*4+3]=vc.w;
            }

            float y = 0.f;
            if (geo) {
                float e1 = __expf(dlt * a[0]);
                float dA = 1.f;
#pragma unroll
                for (int n = 0; n < DSTATE; n++) {
                    dA *= e1;
                    h[n] = dA * h[n] + du * bv[n];
                    y += h[n] * cv[n];
                }
            } else {
#pragma unroll
                for (int n = 0; n < DSTATE; n++) {
                    float dA = __expf(dlt * a[n]);
                    h[n] = dA * h[n] + du * bv[n];
                    y += h[n] * cv[n];
                }
            }
            y += uu * dd;

            float r = xr[m * (2 * DINNER) + DINNER + d];
            float sg = 1.f / (1.f + __expf(-r));
            z[m * DINNER + d] = y * (r * sg);
        }
    }
}

// ---------------- launch ----------------------------------------------------
extern "C" void kernel_launch(void* const* d_in, const int* in_sizes, int n_in,
                              void* d_out, int out_size)
{
    (void)in_sizes; (void)n_in; (void)out_size;
    const float* x    = (const float*)d_in[0];
    const float* ipw  = (const float*)d_in[1];
    const float* ipb  = (const float*)d_in[2];
    const float* cw   = (const float*)d_in[3];
    const float* cb   = (const float*)d_in[4];
    const float* xpw  = (const float*)d_in[5];
    const float* dpw  = (const float*)d_in[6];
    const float* dpb  = (const float*)d_in[7];
    const float* alog = (const float*)d_in[8];
    const float* dvec = (const float*)d_in[9];
    const float* opw  = (const float*)d_in[10];
    const float* opb  = (const float*)d_in[11];
    float* out = (float*)d_out;

    float *xr, *xc, *xdbl, *dlt, *z;
    cudaGetSymbolAddress((void**)&xr,   g_xr);
    cudaGetSymbolAddress((void**)&xc,   g_xc);
    cudaGetSymbolAddress((void**)&xdbl, g_xdbl);
    cudaGetSymbolAddress((void**)&dlt,  g_dlt);
    cudaGetSymbolAddress((void**)&z,    g_z);

    // 1) xr = x @ in_proj_w^T + b      [8192,1024] x [4096,1024] -> [8192,4096]
    gemm_nt<128,128,16,8,8,0><<<dim3(2*DINNER/128, MTOT/128), 256>>>(
        x, DMODEL, ipw, DMODEL, xr, 2*DINNER, ipb, DMODEL);

    // 2) depthwise conv over xc half
    conv_k<<<(MTOT*DINNER)/256, 256>>>(xr, cw, cb, xc);

    // 3) x_dbl = xc @ x_proj_w^T       [8192,2048] x [160,2048] -> [8192,160]
    gemm_nt<64,160,32,4,10,0><<<dim3(1, MTOT/64), 256>>>(
        xc, DINNER, xpw, DINNER, xdbl, XPDIM, nullptr, DINNER);

    // 4) delta = softplus(d_dt @ dt_proj_w^T + b)   [8192,128] x [2048,128]
    gemm_nt<128,128,16,8,8,1><<<dim3(DINNER/128, MTOT/128), 256>>>(
        xdbl, XPDIM, dpw, DTRANK, dlt, DINNER, dpb, DTRANK);

    // 5) selective scan + D skip + silu(res) gating -> z
    scan_k<<<BB*(DINNER/SCAN_D), SCAN_D>>>(xdbl, dlt, xc, xr, alog, dvec, z);

    // 6) out = z @ out_proj_w^T + b    [8192,2048] x [1024,2048] -> [8192,1024]
    gemm_nt<128,128,16,8,8,0><<<dim3(DMODEL/128, MTOT/128), 256>>>(
        z, DINNER, opw, DINNER, out, DMODEL, opb, DINNER);
}

// round 4
// speedup vs baseline: 3.2051x; 3.2051x over previous
#include <cuda_runtime.h>
#include <cuda_bf16.h>
#include <cstdint>
#include <math.h>

#define BB 4
#define LSEQ 2048
#define DMODEL 1024
#define DINNER 2048
#define DSTATE 16
#define DTRANK 128
#define XPDIM 160
#define MTOT (BB*LSEQ)      // 8192

typedef __nv_bfloat16 bf16;

// ---------------- scratch ----------------------------------------------------
static __device__ float g_xr  [(size_t)MTOT * 2 * DINNER];
static __device__ float g_xc  [(size_t)MTOT * DINNER];
static __device__ float g_xdbl[(size_t)MTOT * XPDIM];
static __device__ float g_dlt [(size_t)MTOT * DINNER];

static __device__ bf16 g_xh [(size_t)MTOT * DMODEL];
static __device__ bf16 g_xl [(size_t)MTOT * DMODEL];
static __device__ bf16 g_ipwh[(size_t)2*DINNER * DMODEL];
static __device__ bf16 g_ipwl[(size_t)2*DINNER * DMODEL];
static __device__ bf16 g_xch[(size_t)MTOT * DINNER];
static __device__ bf16 g_xcl[(size_t)MTOT * DINNER];
static __device__ bf16 g_xpwh[(size_t)XPDIM * DINNER];
static __device__ bf16 g_xpwl[(size_t)XPDIM * DINNER];
static __device__ bf16 g_xdh[(size_t)MTOT * XPDIM];
static __device__ bf16 g_xdl[(size_t)MTOT * XPDIM];
static __device__ bf16 g_dpwh[(size_t)DINNER * DTRANK];
static __device__ bf16 g_dpwl[(size_t)DINNER * DTRANK];
static __device__ bf16 g_zh [(size_t)MTOT * DINNER];
static __device__ bf16 g_zl [(size_t)MTOT * DINNER];
static __device__ bf16 g_opwh[(size_t)DMODEL * DINNER];
static __device__ bf16 g_opwl[(size_t)DMODEL * DINNER];

// ---------------- PTX helpers ------------------------------------------------
__device__ __forceinline__ uint32_t smem_u32(const void* p) {
    uint32_t a;
    asm("{ .reg .u64 t; cvta.to.shared.u64 t, %1; cvt.u32.u64 %0, t; }" : "=r"(a) : "l"(p));
    return a;
}
__device__ __forceinline__ void cpa16(uint32_t s, const void* g) {
    asm volatile("cp.async.cg.shared.global [%0], [%1], 16;" :: "r"(s), "l"(g));
}
#define CP_COMMIT() asm volatile("cp.async.commit_group;" ::: "memory")
#define CP_WAIT(n)  asm volatile("cp.async.wait_group %0;" :: "n"(n) : "memory")

__device__ __forceinline__ void ldsm4(uint32_t* r, uint32_t a) {
    asm volatile("ldmatrix.sync.aligned.m8n8.x4.shared.b16 {%0,%1,%2,%3}, [%4];"
                 : "=r"(r[0]), "=r"(r[1]), "=r"(r[2]), "=r"(r[3]) : "r"(a));
}
__device__ __forceinline__ void ldsm2(uint32_t* r, uint32_t a) {
    asm volatile("ldmatrix.sync.aligned.m8n8.x2.shared.b16 {%0,%1}, [%2];"
                 : "=r"(r[0]), "=r"(r[1]) : "r"(a));
}
__device__ __forceinline__ void mma16816(float* d, const uint32_t* a, const uint32_t* b) {
    asm volatile(
        "mma.sync.aligned.m16n8k16.row.col.f32.bf16.bf16.f32 "
        "{%0,%1,%2,%3}, {%4,%5,%6,%7}, {%8,%9}, {%0,%1,%2,%3};"
        : "+f"(d[0]), "+f"(d[1]), "+f"(d[2]), "+f"(d[3])
        : "r"(a[0]), "r"(a[1]), "r"(a[2]), "r"(a[3]), "r"(b[0]), "r"(b[1]));
}

// ---------------- fp32 -> bf16 hi/lo split ----------------------------------
__device__ __forceinline__ void bsplit(float v, bf16& h, bf16& l) {
    h = __float2bfloat16(v);
    l = __float2bfloat16(v - __bfloat162float(h));
}
__global__ void split_k(const float* __restrict__ in, bf16* __restrict__ h,
                        bf16* __restrict__ l, int n) {
    int i = blockIdx.x * blockDim.x + threadIdx.x;
    if (i < n) { bf16 hh, ll; bsplit(in[i], hh, ll); h[i] = hh; l[i] = ll; }
}

// ---------------- HMMA GEMM: C[m,n] = sum_k A[m,k]*B[n,k] --------------------
// bf16x3 (Ah*Bh + Ah*Bl + Al*Bh), fp32 acc. Tiles BMxBNx32, cp.async dbl-buf.
template<int BM, int BN, int WARPS_M, int WARPS_N, int EPI>  // EPI: 0 none, 1 softplus
__global__ void __launch_bounds__(WARPS_M * WARPS_N * 32)
gemm_mma(const bf16* __restrict__ Ah, const bf16* __restrict__ Al, int lda,
         const bf16* __restrict__ Bh, const bf16* __restrict__ Bl, int ldb,
         float* __restrict__ C, int ldc, const float* __restrict__ bias, int K,
         bf16* __restrict__ Ch, bf16* __restrict__ Cl)
{
    constexpr int NT = WARPS_M * WARPS_N * 32;
    constexpr int SA = BM * 80;              // bytes, row stride 40 bf16
    constexpr int SB = BN * 80;
    constexpr int STAGE = 2 * SA + 2 * SB;
    constexpr int WM = BM / WARPS_M, WN = BN / WARPS_N;
    constexpr int IM = WM / 16, JN = WN / 8;

    extern __shared__ char smem[];
    const uint32_t sbase = smem_u32(smem);
    const int tid = threadIdx.x;
    const int warp = tid >> 5, lane = tid & 31;
    const int wm0 = (warp / WARPS_N) * WM;
    const int wn0 = (warp % WARPS_N) * WN;
    const int m0 = blockIdx.y * BM, n0 = blockIdx.x * BN;
    const int NC = K >> 5;

    float acc[IM][JN][4];
#pragma unroll
    for (int i = 0; i < IM; i++)
#pragma unroll
        for (int j = 0; j < JN; j++)
#pragma unroll
            for (int q = 0; q < 4; q++) acc[i][j][q] = 0.f;

    auto load_chunk = [&](int kc, int buf) {
        const int k0 = kc << 5;
        const uint32_t st = sbase + buf * STAGE;
        for (int idx = tid; idx < BM * 4; idx += NT) {
            int r = idx >> 2, c = idx & 3;
            uint32_t off = (uint32_t)(r * 80 + c * 16);
            size_t g = (size_t)(m0 + r) * lda + k0 + c * 8;
            cpa16(st + off, Ah + g);
            cpa16(st + SA + off, Al + g);
        }
        for (int idx = tid; idx < BN * 4; idx += NT) {
            int r = idx >> 2, c = idx & 3;
            uint32_t off = (uint32_t)(r * 80 + c * 16);
            size_t g = (size_t)(n0 + r) * ldb + k0 + c * 8;
            cpa16(st + 2 * SA + off, Bh + g);
            cpa16(st + 2 * SA + SB + off, Bl + g);
        }
        CP_COMMIT();
    };

    load_chunk(0, 0);
    for (int i = 0; i < NC; i++) {
        if (i + 1 < NC) { load_chunk(i + 1, (i + 1) & 1); CP_WAIT(1); }
        else            { CP_WAIT(0); }
        __syncthreads();

        const uint32_t st = sbase + (i & 1) * STAGE;
        const uint32_t a_row = (uint32_t)(wm0 + (lane & 15));
        const uint32_t a_col = (uint32_t)((lane >> 4) * 8);
        const uint32_t b_row = (uint32_t)(wn0 + (lane & 7));
        const uint32_t b_col = (uint32_t)(((lane >> 3) & 1) * 8);

#pragma unroll
        for (int ks = 0; ks < 2; ks++) {
            uint32_t ah[IM][4], al[IM][4], bh[JN][2], bl[JN][2];
#pragma unroll
            for (int im = 0; im < IM; im++) {
                uint32_t off = (a_row + im * 16) * 80 + (ks * 16 + a_col) * 2;
                ldsm4(ah[im], st + off);
                ldsm4(al[im], st + SA + off);
            }
#pragma unroll
            for (int jn = 0; jn < JN; jn++) {
                uint32_t off = (b_row + jn * 8) * 80 + (ks * 16 + b_col) * 2;
                ldsm2(bh[jn], st + 2 * SA + off);
                ldsm2(bl[jn], st + 2 * SA + SB + off);
            }
#pragma unroll
            for (int im = 0; im < IM; im++)
#pragma unroll
                for (int jn = 0; jn < JN; jn++) {
                    mma16816(acc[im][jn], ah[im], bh[jn]);
                    mma16816(acc[im][jn], ah[im], bl[jn]);
                    mma16816(acc[im][jn], al[im], bh[jn]);
                }
        }
        __syncthreads();
    }

    // epilogue
#pragma unroll
    for (int im = 0; im < IM; im++) {
#pragma unroll
        for (int jn = 0; jn < JN; jn++) {
            int r = m0 + wm0 + im * 16 + (lane >> 2);
            int c = n0 + wn0 + jn * 8 + (lane & 3) * 2;
#pragma unroll
            for (int half = 0; half < 2; half++) {
                int rr = r + half * 8;
                float t0 = acc[im][jn][half * 2 + 0];
                float t1 = acc[im][jn][half * 2 + 1];
                if (bias) { t0 += bias[c]; t1 += bias[c + 1]; }
                if (EPI == 1) {
                    t0 = fmaxf(t0, 0.f) + log1pf(expf(-fabsf(t0)));
                    t1 = fmaxf(t1, 0.f) + log1pf(expf(-fabsf(t1)));
                }
                *(float2*)(C + (size_t)rr * ldc + c) = make_float2(t0, t1);
                if (Ch) {
                    bf16 h0, l0, h1, l1;
                    bsplit(t0, h0, l0); bsplit(t1, h1, l1);
                    size_t o = (size_t)rr * ldc + c;
                    Ch[o] = h0; Cl[o] = l0; Ch[o + 1] = h1; Cl[o + 1] = l1;
                }
            }
        }
    }
}

// ---------------- depthwise conv1d, k=4, pad (1,2) + bf16 pair emit ----------
__global__ void conv_k(const float* __restrict__ xr, const float* __restrict__ w,
                       const float* __restrict__ cb, float* __restrict__ out,
                       bf16* __restrict__ oh, bf16* __restrict__ ol)
{
    int idx = blockIdx.x * blockDim.x + threadIdx.x;
    if (idx >= MTOT * DINNER) return;
    int d = idx % DINNER;
    int m = idx / DINNER;
    int t = m % LSEQ, b = m / LSEQ;
    float acc = cb[d];
#pragma unroll
    for (int j = 0; j < 4; j++) {
        int tt = t - 1 + j;
        if (tt >= 0 && tt < LSEQ)
            acc += w[d * 4 + j] * xr[(size_t)(b * LSEQ + tt) * (2 * DINNER) + d];
    }
    out[idx] = acc;
    bf16 hh, ll; bsplit(acc, hh, ll);
    oh[idx] = hh; ol[idx] = ll;
}

// ---------------- selective scan + D skip + silu gating (cp.async staged) ----
#define ST 64
#define SCD 64
__global__ void __launch_bounds__(SCD)
scan_k(const float* __restrict__ xdbl, const float* __restrict__ delta,
       const float* __restrict__ u, const float* __restrict__ xr,
       const float* __restrict__ Alog, const float* __restrict__ Dp,
       bf16* __restrict__ zh, bf16* __restrict__ zl)
{
    extern __shared__ float sm[];
    float* sD  = sm;                 // [2][ST*64]
    float* sU  = sm + 2 * ST * 64;
    float* sR  = sm + 4 * ST * 64;
    float* sBC = sm + 6 * ST * 64;   // [2][ST*32]
    const uint32_t sbase = smem_u32(sm);

    const int tid = threadIdx.x;
    const int b = blockIdx.x / (DINNER / SCD);
    const int d0 = (blockIdx.x % (DINNER / SCD)) * SCD;
    const int d = d0 + tid;

    float a[DSTATE];
#pragma unroll
    for (int n = 0; n < DSTATE; n++) a[n] = -__expf(Alog[d * DSTATE + n]);
    bool geo = true;
#pragma unroll
    for (int n = 1; n < DSTATE; n++)
        geo = geo && (fabsf(a[n] - (float)(n + 1) * a[0]) <= 1e-4f * (float)(n + 1) * fabsf(a[0]));

    const float dd = Dp[d];
    float h[DSTATE];
#pragma unroll
    for (int n = 0; n < DSTATE; n++) h[n] = 0.f;

    auto stage = [&](int c, int buf) {
        const int t0 = c * ST;
        for (int i = tid; i < ST * 16; i += SCD) {
            int t = i >> 4, q = i & 15;
            size_t m = (size_t)(b * LSEQ + t0 + t);
            uint32_t so = (uint32_t)((buf * ST * 64 + t * 64 + q * 4) * 4);
            cpa16(sbase + so, delta + m * DINNER + d0 + q * 4);
            cpa16(sbase + 2 * ST * 64 * 4 + so, u + m * DINNER + d0 + q * 4);
            cpa16(sbase + 4 * ST * 64 * 4 + so, xr + m * (2 * DINNER) + DINNER + d0 + q * 4);
        }
        for (int i = tid; i < ST * 8; i += SCD) {
            int t = i >> 3, q = i & 7;
            uint32_t so = (uint32_t)(6 * ST * 64 * 4 + (buf * ST * 32 + t * 32 + q * 4) * 4);
            cpa16(sbase + so, xdbl + (size_t)(b * LSEQ + t0 + t) * XPDIM + DTRANK + q * 4);
        }
        CP_COMMIT();
    };

    const int NCH = LSEQ / ST;
    stage(0, 0);
    for (int c = 0; c < NCH; c++) {
        const int buf = c & 1;
        if (c + 1 < NCH) { stage(c + 1, (c + 1) & 1); CP_WAIT(1); }
        else             { CP_WAIT(0); }
        __syncthreads();

        const float* pD  = sD  + buf * ST * 64;
        const float* pU  = sU  + buf * ST * 64;
        const float* pR  = sR  + buf * ST * 64;
        const float* pBC = sBC + buf * ST * 32;

        for (int tt = 0; tt < ST; tt++) {
            float dlt = pD[tt * 64 + tid];
            float uu  = pU[tt * 64 + tid];
            float rr  = pR[tt * 64 + tid];
            float du = dlt * uu;

            float bv[DSTATE], cv[DSTATE];
#pragma unroll
            for (int q = 0; q < 4; q++) {
                float4 vb = *(const float4*)(pBC + tt * 32 + q * 4);
                bv[q*4+0]=vb.x; bv[q*4+1]=vb.y; bv[q*4+2]=vb.z; bv[q*4+3]=vb.w;
                float4 vc = *(const float4*)(pBC + tt * 32 + 16 + q * 4);
                cv[q*4+0]=vc.x; cv[q*4+1]=vc.y; cv[q*4+2]=vc.z; cv[q*4+3]=vc.w;
            }

            float y0 = 0.f, y1 = 0.f, y2 = 0.f, y3 = 0.f;
            if (geo) {
                float p[DSTATE];
                p[0] = __expf(dlt * a[0]);
#pragma unroll
                for (int n = 1; n < DSTATE; n++) p[n] = p[(n - 1) >> 1] * p[n >> 1];
#pragma unroll
                for (int n = 0; n < DSTATE; n++) {
                    h[n] = p[n] * h[n] + du * bv[n];
                    float t = h[n] * cv[n];
                    if ((n & 3) == 0) y0 += t; else if ((n & 3) == 1) y1 += t;
                    else if ((n & 3) == 2) y2 += t; else y3 += t;
                }
            } else {
#pragma unroll
                for (int n = 0; n < DSTATE; n++) {
                    float dA = __expf(dlt * a[n]);
                    h[n] = dA * h[n] + du * bv[n];
                    float t = h[n] * cv[n];
                    if ((n & 3) == 0) y0 += t; else if ((n & 3) == 1) y1 += t;
                    else if ((n & 3) == 2) y2 += t; else y3 += t;
                }
            }
            float y = (y0 + y1) + (y2 + y3) + uu * dd;

            float sg = 1.f / (1.f + __expf(-rr));
            float val = y * (rr * sg);
            size_t m = (size_t)(b * LSEQ + c * ST + tt);
            bf16 hh, ll; bsplit(val, hh, ll);
            zh[m * DINNER + d] = hh;
            zl[m * DINNER + d] = ll;
        }
        __syncthreads();
    }
}

// ---------------- launch -----------------------------------------------------
extern "C" void kernel_launch(void* const* d_in, const int* in_sizes, int n_in,
                              void* d_out, int out_size)
{
    (void)in_sizes; (void)n_in; (void)out_size;
    const float* x    = (const float*)d_in[0];
    const float* ipw  = (const float*)d_in[1];
    const float* ipb  = (const float*)d_in[2];
    const float* cw   = (const float*)d_in[3];
    const float* cb   = (const float*)d_in[4];
    const float* xpw  = (const float*)d_in[5];
    const float* dpw  = (const float*)d_in[6];
    const float* dpb  = (const float*)d_in[7];
    const float* alog = (const float*)d_in[8];
    const float* dvec = (const float*)d_in[9];
    const float* opw  = (const float*)d_in[10];
    const float* opb  = (const float*)d_in[11];
    float* out = (float*)d_out;

    float *xr, *xc, *xdbl, *dlt;
    cudaGetSymbolAddress((void**)&xr,   g_xr);
    cudaGetSymbolAddress((void**)&xc,   g_xc);
    cudaGetSymbolAddress((void**)&xdbl, g_xdbl);
    cudaGetSymbolAddress((void**)&dlt,  g_dlt);
    bf16 *xh,*xl,*ipwh,*ipwl,*xch,*xcl,*xpwh,*xpwl,*xdh,*xdl,*dpwh,*dpwl,*zh,*zl,*opwh,*opwl;
    cudaGetSymbolAddress((void**)&xh, g_xh);     cudaGetSymbolAddress((void**)&xl, g_xl);
    cudaGetSymbolAddress((void**)&ipwh, g_ipwh); cudaGetSymbolAddress((void**)&ipwl, g_ipwl);
    cudaGetSymbolAddress((void**)&xch, g_xch);   cudaGetSymbolAddress((void**)&xcl, g_xcl);
    cudaGetSymbolAddress((void**)&xpwh, g_xpwh); cudaGetSymbolAddress((void**)&xpwl, g_xpwl);
    cudaGetSymbolAddress((void**)&xdh, g_xdh);   cudaGetSymbolAddress((void**)&xdl, g_xdl);
    cudaGetSymbolAddress((void**)&dpwh, g_dpwh); cudaGetSymbolAddress((void**)&dpwl, g_dpwl);
    cudaGetSymbolAddress((void**)&zh, g_zh);     cudaGetSymbolAddress((void**)&zl, g_zl);
    cudaGetSymbolAddress((void**)&opwh, g_opwh); cudaGetSymbolAddress((void**)&opwl, g_opwl);

    constexpr int SM128 = 2 * (2 * 128 * 80 + 2 * 128 * 80);  // 81920
    constexpr int SM32  = 2 * (2 * 128 * 80 + 2 * 32 * 80);   // 51200
    constexpr int SMEM_SCAN = (6 * ST * 64 + 2 * ST * 32) * 4; // 114688
    cudaFuncSetAttribute((const void*)gemm_mma<128,128,2,4,0>, cudaFuncAttributeMaxDynamicSharedMemorySize, SM128);
    cudaFuncSetAttribute((const void*)gemm_mma<128,128,2,4,1>, cudaFuncAttributeMaxDynamicSharedMemorySize, SM128);
    cudaFuncSetAttribute((const void*)gemm_mma<128,32,8,1,0>,  cudaFuncAttributeMaxDynamicSharedMemorySize, SM32);
    cudaFuncSetAttribute((const void*)scan_k, cudaFuncAttributeMaxDynamicSharedMemorySize, SMEM_SCAN);

    // 0) splits
    split_k<<<(MTOT*DMODEL)/256, 256>>>(x, xh, xl, MTOT*DMODEL);
    split_k<<<(2*DINNER*DMODEL)/256, 256>>>(ipw, ipwh, ipwl, 2*DINNER*DMODEL);
    split_k<<<(XPDIM*DINNER)/256, 256>>>(xpw, xpwh, xpwl, XPDIM*DINNER);
    split_k<<<(DINNER*DTRANK)/256, 256>>>(dpw, dpwh, dpwl, DINNER*DTRANK);
    split_k<<<(DMODEL*DINNER)/256, 256>>>(opw, opwh, opwl, DMODEL*DINNER);

    // 1) in_proj: [8192,1024] x [4096,1024]^T -> xr [8192,4096]
    gemm_mma<128,128,2,4,0><<<dim3(2*DINNER/128, MTOT/128), 256, SM128>>>(
        xh, xl, DMODEL, ipwh, ipwl, DMODEL, xr, 2*DINNER, ipb, DMODEL, nullptr, nullptr);

    // 2) depthwise conv -> xc (fp32 + bf16 pair)
    conv_k<<<(MTOT*DINNER)/256, 256>>>(xr, cw, cb, xc, xch, xcl);

    // 3) x_proj: [8192,2048] x [160,2048]^T -> xdbl [8192,160] (+ bf16 pair)
    gemm_mma<128,32,8,1,0><<<dim3(XPDIM/32, MTOT/128), 256, SM32>>>(
        xch, xcl, DINNER, xpwh, xpwl, DINNER, xdbl, XPDIM, nullptr, DINNER, xdh, xdl);

    // 4) dt_proj + softplus: [8192,128] x [2048,128]^T -> dlt [8192,2048]
    gemm_mma<128,128,2,4,1><<<dim3(DINNER/128, MTOT/128), 256, SM128>>>(
        xdh, xdl, XPDIM, dpwh, dpwl, DTRANK, dlt, DINNER, dpb, DTRANK, nullptr, nullptr);

    // 5) selective scan + D skip + silu gating -> z (bf16 pair)
    scan_k<<<BB*(DINNER/SCD), SCD, SMEM_SCAN>>>(xdbl, dlt, xc, xr, alog, dvec, zh, zl);

    // 6) out_proj: [8192,2048] x [1024,2048]^T -> out [8192,1024]
    gemm_mma<128,128,2,4,0><<<dim3(DMODEL/128, MTOT/128), 256, SM128>>>(
        zh, zl, DINNER, opwh, opwl, DINNER, out, DMODEL, opb, DINNER, nullptr, nullptr);
}

// round 5
// speedup vs baseline: 3.9062x; 1.2187x over previous
#include <cuda_runtime.h>
#include <cuda_bf16.h>
#include <cstdint>
#include <math.h>

#define BB 4
#define LSEQ 2048
#define DMODEL 1024
#define DINNER 2048
#define DSTATE 16
#define DTRANK 128
#define XPDIM 160
#define MTOT (BB*LSEQ)      // 8192

// ---------------- scratch ----------------------------------------------------
static __device__ float g_xr  [(size_t)MTOT * 2 * DINNER];  // in_proj out (xc | res)
static __device__ float g_xc  [(size_t)MTOT * DINNER];      // conv out (tf32-rounded)
static __device__ float g_xdbl[(size_t)MTOT * XPDIM];       // x_proj out (tf32-rounded)
static __device__ float g_dlt [(size_t)MTOT * DINNER];      // softplus(dt_proj)
static __device__ float g_z   [(size_t)MTOT * DINNER];      // gated scan out (tf32-rounded)
// tf32-rounded copies of harness inputs used as GEMM operands
static __device__ float g_xt  [(size_t)MTOT * DMODEL];
static __device__ float g_ipt [(size_t)2*DINNER * DMODEL];
static __device__ float g_xpt [(size_t)XPDIM * DINNER];
static __device__ float g_dpt [(size_t)DINNER * DTRANK];
static __device__ float g_opt [(size_t)DMODEL * DINNER];

// ---------------- PTX helpers ------------------------------------------------
__device__ __forceinline__ uint32_t smem_u32(const void* p) {
    uint32_t a;
    asm("{ .reg .u64 t; cvta.to.shared.u64 t, %1; cvt.u32.u64 %0, t; }" : "=r"(a) : "l"(p));
    return a;
}
__device__ __forceinline__ void cpa16(uint32_t s, const void* g) {
    asm volatile("cp.async.cg.shared.global [%0], [%1], 16;" :: "r"(s), "l"(g));
}
#define CP_COMMIT() asm volatile("cp.async.commit_group;" ::: "memory")
#define CP_WAIT(n)  asm volatile("cp.async.wait_group %0;" :: "n"(n) : "memory")

__device__ __forceinline__ void ldsm4(uint32_t* r, uint32_t a) {
    asm volatile("ldmatrix.sync.aligned.m8n8.x4.shared.b16 {%0,%1,%2,%3}, [%4];"
                 : "=r"(r[0]), "=r"(r[1]), "=r"(r[2]), "=r"(r[3]) : "r"(a));
}
__device__ __forceinline__ void ldsm2(uint32_t* r, uint32_t a) {
    asm volatile("ldmatrix.sync.aligned.m8n8.x2.shared.b16 {%0,%1}, [%2];"
                 : "=r"(r[0]), "=r"(r[1]) : "r"(a));
}
// tf32 mma: m16n8k8, fp32 accumulate
__device__ __forceinline__ void mma1688(float* d, const uint32_t* a, const uint32_t* b) {
    asm volatile(
        "mma.sync.aligned.m16n8k8.row.col.f32.tf32.tf32.f32 "
        "{%0,%1,%2,%3}, {%4,%5,%6,%7}, {%8,%9}, {%0,%1,%2,%3};"
        : "+f"(d[0]), "+f"(d[1]), "+f"(d[2]), "+f"(d[3])
        : "r"(a[0]), "r"(a[1]), "r"(a[2]), "r"(a[3]), "r"(b[0]), "r"(b[1]));
}
// round-to-nearest into tf32 (zeroes low 13 mantissa bits, unbiased)
__device__ __forceinline__ float rtf(float v) {
    uint32_t r;
    asm("cvt.rna.tf32.f32 %0, %1;" : "=r"(r) : "f"(v));
    return __uint_as_float(r);
}

__global__ void round_k(const float* __restrict__ in, float* __restrict__ out, int n) {
    int i = blockIdx.x * blockDim.x + threadIdx.x;
    if (i < n) out[i] = rtf(in[i]);
}

// ---------------- tf32 HMMA GEMM: C[m,n] = sum_k A[m,k]*B[n,k] ---------------
// fp32 operands staged to smem (144B row stride), tf32 mma, fp32 acc.
// Tiles BMxBNx32, cp.async double-buffered.
template<int BM, int BN, int WARPS_M, int WARPS_N, int EPI, int RND>
__global__ void __launch_bounds__(WARPS_M * WARPS_N * 32)
gemm_tf(const float* __restrict__ A, int lda,
        const float* __restrict__ B, int ldb,
        float* __restrict__ C, int ldc, const float* __restrict__ bias, int K)
{
    constexpr int NT = WARPS_M * WARPS_N * 32;
    constexpr int RS = 144;                 // bytes per 32-float row (+16B pad)
    constexpr int SA = BM * RS;
    constexpr int SB = BN * RS;
    constexpr int STAGE = SA + SB;
    constexpr int WM = BM / WARPS_M, WN = BN / WARPS_N;
    constexpr int IM = WM / 16, JN = WN / 8;

    extern __shared__ char smem[];
    const uint32_t sbase = smem_u32(smem);
    const int tid = threadIdx.x;
    const int warp = tid >> 5, lane = tid & 31;
    const int wm0 = (warp / WARPS_N) * WM;
    const int wn0 = (warp % WARPS_N) * WN;
    const int m0 = blockIdx.y * BM, n0 = blockIdx.x * BN;
    const int NC = K >> 5;

    float acc[IM][JN][4];
#pragma unroll
    for (int i = 0; i < IM; i++)
#pragma unroll
        for (int j = 0; j < JN; j++)
#pragma unroll
            for (int q = 0; q < 4; q++) acc[i][j][q] = 0.f;

    auto load_chunk = [&](int kc, int buf) {
        const int k0 = kc << 5;
        const uint32_t st = sbase + buf * STAGE;
        for (int idx = tid; idx < BM * 8; idx += NT) {   // A: BM rows x 8 x 16B
            int r = idx >> 3, c = idx & 7;
            cpa16(st + (uint32_t)(r * RS + c * 16), A + (size_t)(m0 + r) * lda + k0 + c * 4);
        }
        for (int idx = tid; idx < BN * 8; idx += NT) {   // B: BN rows x 8 x 16B
            int r = idx >> 3, c = idx & 7;
            cpa16(st + SA + (uint32_t)(r * RS + c * 16), B + (size_t)(n0 + r) * ldb + k0 + c * 4);
        }
        CP_COMMIT();
    };

    load_chunk(0, 0);
    for (int i = 0; i < NC; i++) {
        if (i + 1 < NC) { load_chunk(i + 1, (i + 1) & 1); CP_WAIT(1); }
        else            { CP_WAIT(0); }
        __syncthreads();

        const uint32_t st = sbase + (i & 1) * STAGE;
        // ldmatrix addressing: fp32 viewed as b16 pairs gives exact tf32 fragments
        const uint32_t a_row = (uint32_t)(wm0 + (lane & 15));
        const uint32_t a_half = (uint32_t)((lane >> 4) * 16);      // bytes
        const uint32_t b_row = (uint32_t)(wn0 + (lane & 7));
        const uint32_t b_half = (uint32_t)(((lane >> 3) & 1) * 16);

#pragma unroll
        for (int ks = 0; ks < 4; ks++) {                 // 4 x K8 per 32-chunk
            uint32_t af[IM][4], bf[JN][2];
#pragma unroll
            for (int im = 0; im < IM; im++)
                ldsm4(af[im], st + (a_row + im * 16) * RS + ks * 32 + a_half);
#pragma unroll
            for (int jn = 0; jn < JN; jn++)
                ldsm2(bf[jn], st + SA + (b_row + jn * 8) * RS + ks * 32 + b_half);
#pragma unroll
            for (int im = 0; im < IM; im++)
#pragma unroll
                for (int jn = 0; jn < JN; jn++)
                    mma1688(acc[im][jn], af[im], bf[jn]);
        }
        __syncthreads();
    }

    // epilogue: c0,c1 -> (r, c),(r, c+1); c2,c3 -> (r+8, ...)
#pragma unroll
    for (int im = 0; im < IM; im++) {
#pragma unroll
        for (int jn = 0; jn < JN; jn++) {
            int r = m0 + wm0 + im * 16 + (lane >> 2);
            int c = n0 + wn0 + jn * 8 + (lane & 3) * 2;
#pragma unroll
            for (int half = 0; half < 2; half++) {
                int rr = r + half * 8;
                float t0 = acc[im][jn][half * 2 + 0];
                float t1 = acc[im][jn][half * 2 + 1];
                if (bias) { t0 += bias[c]; t1 += bias[c + 1]; }
                if (EPI == 1) {
                    t0 = fmaxf(t0, 0.f) + log1pf(expf(-fabsf(t0)));
                    t1 = fmaxf(t1, 0.f) + log1pf(expf(-fabsf(t1)));
                }
                if (RND) { t0 = rtf(t0); t1 = rtf(t1); }
                *(float2*)(C + (size_t)rr * ldc + c) = make_float2(t0, t1);
            }
        }
    }
}

// ---------------- depthwise conv1d, k=4, pad (1,2); out tf32-rounded ---------
__global__ void conv_k(const float* __restrict__ xr, const float* __restrict__ w,
                       const float* __restrict__ cb, float* __restrict__ out)
{
    int idx = blockIdx.x * blockDim.x + threadIdx.x;
    if (idx >= MTOT * DINNER) return;
    int d = idx % DINNER;
    int m = idx / DINNER;
    int t = m % LSEQ, b = m / LSEQ;
    float acc = cb[d];
#pragma unroll
    for (int j = 0; j < 4; j++) {
        int tt = t - 1 + j;
        if (tt >= 0 && tt < LSEQ)
            acc += w[d * 4 + j] * xr[(size_t)(b * LSEQ + tt) * (2 * DINNER) + d];
    }
    out[idx] = rtf(acc);   // feeds x_proj A operand; 1.2e-4 rel rounding, fine for scan u
}

// ---------------- selective scan + D skip + silu gating (cp.async staged) ----
#define ST 64
#define SCD 64
__global__ void __launch_bounds__(SCD)
scan_k(const float* __restrict__ xdbl, const float* __restrict__ delta,
       const float* __restrict__ u, const float* __restrict__ xr,
       const float* __restrict__ Alog, const float* __restrict__ Dp,
       float* __restrict__ z)
{
    extern __shared__ float sm[];
    float* sD  = sm;                 // [2][ST*64]
    float* sU  = sm + 2 * ST * 64;
    float* sR  = sm + 4 * ST * 64;
    float* sBC = sm + 6 * ST * 64;   // [2][ST*32]
    const uint32_t sbase = smem_u32(sm);

    const int tid = threadIdx.x;
    const int b = blockIdx.x / (DINNER / SCD);
    const int d0 = (blockIdx.x % (DINNER / SCD)) * SCD;
    const int d = d0 + tid;

    float a[DSTATE];
#pragma unroll
    for (int n = 0; n < DSTATE; n++) a[n] = -__expf(Alog[d * DSTATE + n]);
    bool geo = true;
#pragma unroll
    for (int n = 1; n < DSTATE; n++)
        geo = geo && (fabsf(a[n] - (float)(n + 1) * a[0]) <= 1e-4f * (float)(n + 1) * fabsf(a[0]));

    const float dd = Dp[d];
    float h[DSTATE];
#pragma unroll
    for (int n = 0; n < DSTATE; n++) h[n] = 0.f;

    auto stage = [&](int c, int buf) {
        const int t0 = c * ST;
        for (int i = tid; i < ST * 16; i += SCD) {
            int t = i >> 4, q = i & 15;
            size_t m = (size_t)(b * LSEQ + t0 + t);
            uint32_t so = (uint32_t)((buf * ST * 64 + t * 64 + q * 4) * 4);
            cpa16(sbase + so, delta + m * DINNER + d0 + q * 4);
            cpa16(sbase + 2 * ST * 64 * 4 + so, u + m * DINNER + d0 + q * 4);
            cpa16(sbase + 4 * ST * 64 * 4 + so, xr + m * (2 * DINNER) + DINNER + d0 + q * 4);
        }
        for (int i = tid; i < ST * 8; i += SCD) {
            int t = i >> 3, q = i & 7;
            uint32_t so = (uint32_t)(6 * ST * 64 * 4 + (buf * ST * 32 + t * 32 + q * 4) * 4);
            cpa16(sbase + so, xdbl + (size_t)(b * LSEQ + t0 + t) * XPDIM + DTRANK + q * 4);
        }
        CP_COMMIT();
    };

    const int NCH = LSEQ / ST;
    stage(0, 0);
    for (int c = 0; c < NCH; c++) {
        const int buf = c & 1;
        if (c + 1 < NCH) { stage(c + 1, (c + 1) & 1); CP_WAIT(1); }
        else             { CP_WAIT(0); }
        __syncthreads();

        const float* pD  = sD  + buf * ST * 64;
        const float* pU  = sU  + buf * ST * 64;
        const float* pR  = sR  + buf * ST * 64;
        const float* pBC = sBC + buf * ST * 32;

        for (int tt = 0; tt < ST; tt++) {
            float dlt = pD[tt * 64 + tid];
            float uu  = pU[tt * 64 + tid];
            float rr  = pR[tt * 64 + tid];
            float du = dlt * uu;

            float bv[DSTATE], cv[DSTATE];
#pragma unroll
            for (int q = 0; q < 4; q++) {
                float4 vb = *(const float4*)(pBC + tt * 32 + q * 4);
                bv[q*4+0]=vb.x; bv[q*4+1]=vb.y; bv[q*4+2]=vb.z; bv[q*4+3]=vb.w;
                float4 vc = *(const float4*)(pBC + tt * 32 + 16 + q * 4);
                cv[q*4+0]=vc.x; cv[q*4+1]=vc.y; cv[q*4+2]=vc.z; cv[q*4+3]=vc.w;
            }

            float y0 = 0.f, y1 = 0.f, y2 = 0.f, y3 = 0.f;
            if (geo) {
                float p[DSTATE];
                p[0] = __expf(dlt * a[0]);
#pragma unroll
                for (int n = 1; n < DSTATE; n++) p[n] = p[(n - 1) >> 1] * p[n >> 1];
#pragma unroll
                for (int n = 0; n < DSTATE; n++) {
                    h[n] = p[n] * h[n] + du * bv[n];
                    float t = h[n] * cv[n];
                    if ((n & 3) == 0) y0 += t; else if ((n & 3) == 1) y1 += t;
                    else if ((n & 3) == 2) y2 += t; else y3 += t;
                }
            } else {
#pragma unroll
                for (int n = 0; n < DSTATE; n++) {
                    float dA = __expf(dlt * a[n]);
                    h[n] = dA * h[n] + du * bv[n];
                    float t = h[n] * cv[n];
                    if ((n & 3) == 0) y0 += t; else if ((n & 3) == 1) y1 += t;
                    else if ((n & 3) == 2) y2 += t; else y3 += t;
                }
            }
            float y = (y0 + y1) + (y2 + y3) + uu * dd;

            float sg = 1.f / (1.f + __expf(-rr));
            size_t m = (size_t)(b * LSEQ + c * ST + tt);
            z[m * DINNER + d] = rtf(y * (rr * sg));   // feeds out_proj A
        }
        __syncthreads();
    }
}

// ---------------- launch -----------------------------------------------------
extern "C" void kernel_launch(void* const* d_in, const int* in_sizes, int n_in,
                              void* d_out, int out_size)
{
    (void)in_sizes; (void)n_in; (void)out_size;
    const float* x    = (const float*)d_in[0];
    const float* ipw  = (const float*)d_in[1];
    const float* ipb  = (const float*)d_in[2];
    const float* cw   = (const float*)d_in[3];
    const float* cb   = (const float*)d_in[4];
    const float* xpw  = (const float*)d_in[5];
    const float* dpw  = (const float*)d_in[6];
    const float* dpb  = (const float*)d_in[7];
    const float* alog = (const float*)d_in[8];
    const float* dvec = (const float*)d_in[9];
    const float* opw  = (const float*)d_in[10];
    const float* opb  = (const float*)d_in[11];
    float* out = (float*)d_out;

    float *xr, *xc, *xdbl, *dlt, *z, *xt, *ipt, *xpt, *dpt, *opt;
    cudaGetSymbolAddress((void**)&xr,   g_xr);
    cudaGetSymbolAddress((void**)&xc,   g_xc);
    cudaGetSymbolAddress((void**)&xdbl, g_xdbl);
    cudaGetSymbolAddress((void**)&dlt,  g_dlt);
    cudaGetSymbolAddress((void**)&z,    g_z);
    cudaGetSymbolAddress((void**)&xt,   g_xt);
    cudaGetSymbolAddress((void**)&ipt,  g_ipt);
    cudaGetSymbolAddress((void**)&xpt,  g_xpt);
    cudaGetSymbolAddress((void**)&dpt,  g_dpt);
    cudaGetSymbolAddress((void**)&opt,  g_opt);

    constexpr int SM128 = 2 * (128 * 144 + 128 * 144);  // 73728
    constexpr int SM32  = 2 * (128 * 144 + 32 * 144);   // 46080
    constexpr int SMEM_SCAN = (6 * ST * 64 + 2 * ST * 32) * 4; // 114688
    cudaFuncSetAttribute((const void*)gemm_tf<128,128,2,4,0,0>, cudaFuncAttributeMaxDynamicSharedMemorySize, SM128);
    cudaFuncSetAttribute((const void*)gemm_tf<128,128,2,4,1,0>, cudaFuncAttributeMaxDynamicSharedMemorySize, SM128);
    cudaFuncSetAttribute((const void*)gemm_tf<128,32,8,1,0,1>,  cudaFuncAttributeMaxDynamicSharedMemorySize, SM32);
    cudaFuncSetAttribute((const void*)scan_k, cudaFuncAttributeMaxDynamicSharedMemorySize, SMEM_SCAN);

    // 0) tf32 pre-rounding (unbiased RNA) of GEMM operands from harness inputs
    round_k<<<(MTOT*DMODEL)/256, 256>>>(x, xt, MTOT*DMODEL);
    round_k<<<(2*DINNER*DMODEL)/256, 256>>>(ipw, ipt, 2*DINNER*DMODEL);
    round_k<<<(XPDIM*DINNER)/256, 256>>>(xpw, xpt, XPDIM*DINNER);
    round_k<<<(DINNER*DTRANK)/256, 256>>>(dpw, dpt, DINNER*DTRANK);
    round_k<<<(DMODEL*DINNER)/256, 256>>>(opw, opt, DMODEL*DINNER);

    // 1) in_proj: [8192,1024] x [4096,1024]^T -> xr [8192,4096]
    gemm_tf<128,128,2,4,0,0><<<dim3(2*DINNER/128, MTOT/128), 256, SM128>>>(
        xt, DMODEL, ipt, DMODEL, xr, 2*DINNER, ipb, DMODEL);

    // 2) depthwise conv -> xc (tf32-rounded)
    conv_k<<<(MTOT*DINNER)/256, 256>>>(xr, cw, cb, xc);

    // 3) x_proj: [8192,2048] x [160,2048]^T -> xdbl [8192,160] (tf32-rounded)
    gemm_tf<128,32,8,1,0,1><<<dim3(XPDIM/32, MTOT/128), 256, SM32>>>(
        xc, DINNER, xpt, DINNER, xdbl, XPDIM, nullptr, DINNER);

    // 4) dt_proj + softplus: [8192,128(of 160)] x [2048,128]^T -> dlt [8192,2048]
    gemm_tf<128,128,2,4,1,0><<<dim3(DINNER/128, MTOT/128), 256, SM128>>>(
        xdbl, XPDIM, dpt, DTRANK, dlt, DINNER, dpb, DTRANK);

    // 5) selective scan + D skip + silu gating -> z (tf32-rounded)
    scan_k<<<BB*(DINNER/SCD), SCD, SMEM_SCAN>>>(xdbl, dlt, xc, xr, alog, dvec, z);

    // 6) out_proj: [8192,2048] x [1024,2048]^T -> out [8192,1024]
    gemm_tf<128,128,2,4,0,0><<<dim3(DMODEL/128, MTOT/128), 256, SM128>>>(
        z, DINNER, opt, DINNER, out, DMODEL, opb, DINNER);
}